// round 15
// baseline (speedup 1.0000x reference)
#include <cuda_runtime.h>
#include <cuda_bf16.h>
#include <cstdint>

// Problem constants
#define T_STEPS 2048
#define R_DIM   1024
#define B_DIM   8
#define H_DIM   256
#define I_DIM   128
#define NTHR    256

__device__ float g_uin[(size_t)T_STEPS * R_DIM * B_DIM];   // [t][r][b]

// ---------------------------------------------------------------------------
// Helpers
// ---------------------------------------------------------------------------
__device__ __forceinline__ uint32_t smem_u32(const void* p) {
    uint32_t a;
    asm("{ .reg .u64 t; cvta.to.shared.u64 t, %1; cvt.u32.u64 %0, t; }"
        : "=r"(a) : "l"(p));
    return a;
}
__device__ __forceinline__ void st_cluster_f32(uint32_t laddr, int rank, float v) {
    uint32_t rem;
    asm volatile("mapa.shared::cluster.u32 %0, %1, %2;"
                 : "=r"(rem) : "r"(laddr), "r"(rank));
    asm volatile("st.shared::cluster.f32 [%0], %1;" :: "r"(rem), "f"(v) : "memory");
}

__host__ __device__ constexpr int ilog2c(int n) {
    return n <= 1 ? 0 : 1 + ilog2c(n / 2);
}

// Butterfly reduction of N per-thread values across 32 lanes.
// Post: lane l holds the full sum of value index v = l >> log2(32/N).
template <int N>
__device__ __forceinline__ void butterfly_reduce(float* acc, int lane) {
    int n = N;
#pragma unroll
    for (int off = 16; off >= 1; off >>= 1) {
        if (n > 1) {
            const int h = n >> 1;
            const bool up = (lane & off) != 0;
#pragma unroll
            for (int i = 0; i < h; ++i) {
                float send = up ? acc[i] : acc[i + h];
                float recv = __shfl_xor_sync(0xffffffffu, send, off);
                if (up) acc[i + h] += recv; else acc[i] += recv;
            }
            if (up) {
#pragma unroll
                for (int i = 0; i < h; ++i) acc[i] = acc[i + h];
            }
            n = h;
        } else {
            acc[0] += __shfl_xor_sync(0xffffffffu, acc[0], off);
        }
    }
}

// ---------------------------------------------------------------------------
// Kernel A: uin[t][r][b] = u[b][t][:] . w_in[r][:] + w_bias[r]
// ---------------------------------------------------------------------------
#define UIN_WPAD 132
#define UIN_SMEM (256 * UIN_WPAD * 4 + B_DIM * I_DIM * 4)

__global__ void __launch_bounds__(256) uin_kernel(
    const float* __restrict__ u, const float* __restrict__ w_in,
    const float* __restrict__ w_bias)
{
    extern __shared__ float sm[];
    float* w_s = sm;
    float* u_s = sm + 256 * UIN_WPAD;

    const int tid = threadIdx.x;
    const int r0  = blockIdx.x * 256;
    const int t0  = blockIdx.y * 64;

    for (int j = tid; j < 256 * I_DIM; j += 256) {
        int row = j >> 7, i = j & 127;
        w_s[row * UIN_WPAD + i] = w_in[(r0 + row) * I_DIM + i];
    }
    const float bias = w_bias[r0 + tid];

    for (int tt = 0; tt < 64; ++tt) {
        const int t = t0 + tt;
        __syncthreads();
        for (int j = tid; j < B_DIM * I_DIM; j += 256) {
            int b = j >> 7, i = j & 127;
            u_s[j] = u[((size_t)b * T_STEPS + t) * I_DIM + i];
        }
        __syncthreads();

        float acc[B_DIM];
#pragma unroll
        for (int b = 0; b < B_DIM; ++b) acc[b] = bias;

        const float4* wrow = reinterpret_cast<const float4*>(&w_s[tid * UIN_WPAD]);
#pragma unroll 8
        for (int i4 = 0; i4 < I_DIM / 4; ++i4) {
            float4 w4 = wrow[i4];
#pragma unroll
            for (int b = 0; b < B_DIM; ++b) {
                float4 u4 = reinterpret_cast<const float4*>(&u_s[b * I_DIM])[i4];
                acc[b] = fmaf(w4.x, u4.x, acc[b]);
                acc[b] = fmaf(w4.y, u4.y, acc[b]);
                acc[b] = fmaf(w4.z, u4.z, acc[b]);
                acc[b] = fmaf(w4.w, u4.w, acc[b]);
            }
        }
        float* dst = &g_uin[((size_t)t * R_DIM + r0 + tid) * B_DIM];
        reinterpret_cast<float4*>(dst)[0] = make_float4(acc[0], acc[1], acc[2], acc[3]);
        reinterpret_cast<float4*>(dst)[1] = make_float4(acc[4], acc[5], acc[6], acc[7]);
    }
}

// ---------------------------------------------------------------------------
// Kernel B: cluster-scoped persistent recurrence, ONE batch per cluster.
// 8 clusters x CS CTAs (CS=16 -> 128 SMs). Cluster g owns batch g.
// CTA rank owns R_DIM/CS W rows (CPW*8 cached in SMEM, rest streamed from L2),
// H_DIM/CS pca cols + gate rows. DSMEM broadcast; one barrier.cluster per step.
// ---------------------------------------------------------------------------
#define CPW_OF(CS_)  ((CS_) == 16 ? 3 : 0)
#define ESN_SMEM_F(CS_) ((3072 + CPW_OF(CS_) * 8 * 1024 + (H_DIM/(CS_))*1024 + \
                          (H_DIM/(CS_))*256*2 + (H_DIM/(CS_))) * 4)

// One row x 1 batch dot-product with 4-way split accumulators.
__device__ __forceinline__ float row_mac1(
    const float4* w4, const float* xv, bool from_global)
{
    float a0 = 0.f, a1 = 0.f, a2 = 0.f, a3 = 0.f;
#pragma unroll
    for (int i = 0; i < 8; ++i) {
        const float4 w = from_global ? __ldcg(w4 + 32 * i) : w4[32 * i];
        a0 = fmaf(w.x, xv[4 * i + 0], a0);
        a1 = fmaf(w.y, xv[4 * i + 1], a1);
        a2 = fmaf(w.z, xv[4 * i + 2], a2);
        a3 = fmaf(w.w, xv[4 * i + 3], a3);
    }
    return (a0 + a1) + (a2 + a3);
}

template <int CS>
__global__ void __launch_bounds__(NTHR, 1) esn_cluster(
    const float* __restrict__ w,
    const float* __restrict__ w_pca,
    const float* __restrict__ wzp,
    const float* __restrict__ wzh,
    const float* __restrict__ bz,
    float* __restrict__ out)
{
    constexpr int ROWS = R_DIM / CS;      // W rows per CTA
    constexpr int RPW  = ROWS / 8;        // rows per warp
    constexpr int CPW  = CPW_OF(CS);      // SMEM-cached rows per warp
    constexpr int HC   = H_DIM / CS;      // pca cols / gate rows per CTA
    constexpr int HCW  = HC / 8;          // per warp
    constexpr int NVX  = RPW;             // MAC values per warp (1 batch)
    constexpr int SX   = ilog2c(32 / NVX);
    constexpr int NVP  = HCW;
    constexpr int SP   = ilog2c(32 / NVP);

    extern __shared__ float smf[];
    float* x_s    = smf;                       // [2][1024]
    float* p_s    = x_s + 2048;                // [2][256]
    float* h_s    = p_s + 512;                 // [2][256]
    float* wc_s   = h_s + 512;                 // [CPW*8][1024] cached W rows
    float* wpca_s = wc_s + CPW * 8 * 1024;     // [HC][1024]  (transposed)
    float* wzp_s  = wpca_s + HC * 1024;        // [HC][256]
    float* wzh_s  = wzp_s + HC * 256;          // [HC][256]
    float* bz_s   = wzh_s + HC * 256;          // [HC]

    const int tid  = threadIdx.x;
    const int warp = tid >> 5;
    const int lane = tid & 31;
    unsigned cr;
    asm("mov.u32 %0, %%cluster_ctarank;" : "=r"(cr));
    const int crank = (int)cr;
    const int g   = blockIdx.x / CS;      // batch index (0..7)
    const int r0  = crank * ROWS;
    const int hc0 = crank * HC;

    // ---- one-time staging ----
    for (int j = tid; j < 3072; j += NTHR) smf[j] = 0.f;   // zero x/p/h buffers
    if (CPW > 0) {
        for (int idx = tid; idx < CPW * 8 * 256; idx += NTHR) {
            const int rowi = idx >> 8;
            const int q    = idx & 255;
            const int w_   = rowi / CPW;
            const int rr   = rowi % CPW;
            const float4 v4 = *reinterpret_cast<const float4*>(
                &w[(size_t)(r0 + w_ * RPW + rr) * 1024 + 4 * q]);
            *reinterpret_cast<float4*>(&wc_s[rowi * 1024 + 4 * q]) = v4;
        }
    }
    for (int idx = tid; idx < 1024 * (HC / 4); idx += NTHR) {
        const int r = idx / (HC / 4);
        const int q = idx % (HC / 4);
        const float4 v4 = *reinterpret_cast<const float4*>(
            &w_pca[(size_t)r * H_DIM + hc0 + 4 * q]);
        wpca_s[(4 * q + 0) * 1024 + r] = v4.x;
        wpca_s[(4 * q + 1) * 1024 + r] = v4.y;
        wpca_s[(4 * q + 2) * 1024 + r] = v4.z;
        wpca_s[(4 * q + 3) * 1024 + r] = v4.w;
    }
    for (int j = tid; j < HC * 256; j += NTHR) {
        const int row = j >> 8, q = j & 255;
        wzp_s[j] = wzp[(hc0 + row) * H_DIM + q];
        wzh_s[j] = wzh[(hc0 + row) * H_DIM + q];
    }
    if (tid < HC) bz_s[tid] = bz[hc0 + tid];
    __syncthreads();
    asm volatile("barrier.cluster.arrive.aligned;" ::: "memory");
    asm volatile("barrier.cluster.wait.aligned;"   ::: "memory");

    // ---- main loop: gate(t=k-2) | MAC x_k | pca p_{k-1} | barrier ----
    for (int k = 0; k <= T_STEPS + 1; ++k) {
        const bool do_mac  = (k < T_STEPS);
        const bool do_pca  = (k >= 1 && k <= T_STEPS);
        const bool do_gate = (k >= 2);

        // MAC writer mapping (value v = lane >> SX -> local row)
        const int mrow = lane >> SX;
        const int grow = r0 + warp * RPW + mrow;

        float uin_pref = 0.f;
        if (do_mac)
            uin_pref = __ldcg(&g_uin[((size_t)k * R_DIM + grow) * 8 + g]);

        // ---- gate for t = k-2 ----
        if (do_gate) {
            const int t = k - 2;
            const float* pv = p_s + (t & 1) * 256;
            const float* hv = h_s + ((t + 1) & 1) * 256;
            const bool have_h = (t > 0);

            float ga[NVP];
#pragma unroll
            for (int i = 0; i < NVP; ++i) ga[i] = 0.f;
#pragma unroll
            for (int q = 0; q < 8; ++q) {
                const int j = lane + 32 * q;
                const float pj = pv[j];
                const float hj = have_h ? hv[j] : 0.f;
#pragma unroll
                for (int rr = 0; rr < HCW; ++rr) {
                    const int row = warp * HCW + rr;
                    ga[rr] = fmaf(pj, wzp_s[row * 256 + j],
                             fmaf(hj, wzh_s[row * 256 + j], ga[rr]));
                }
            }
            butterfly_reduce<NVP>(ga, lane);
            if ((lane & ((1 << SP) - 1)) == 0) {
                const int v   = lane >> SP;
                const int row = warp * HCW + v;
                const int hg  = hc0 + row;
                const float s = ga[0] + bz_s[row];
                const float z = 1.f / (1.f + __expf(-s));
                const float po = pv[hg];
                const float ho = have_h ? hv[hg] : 0.f;
                const float hn = (1.f - z) * ho + z * po;
                const uint32_t la = smem_u32(&h_s[(t & 1) * 256 + hg]);
#pragma unroll
                for (int rk = 0; rk < CS; ++rk) st_cluster_f32(la, rk, hn);
                out[((size_t)g * T_STEPS + t) * H_DIM + hg] = hn;
            }
        }

        // ---- load x_{k-1} slice into registers (reused by MAC and pca) ----
        float xv[32];
        if (do_pca) {
            const float* xb = x_s + ((k + 1) & 1) * 1024;
#pragma unroll
            for (int i = 0; i < 8; ++i) {
                const float4 a = *reinterpret_cast<const float4*>(
                    &xb[4 * lane + 128 * i]);
                xv[i * 4 + 0] = a.x; xv[i * 4 + 1] = a.y;
                xv[i * 4 + 2] = a.z; xv[i * 4 + 3] = a.w;
            }
        }

        // ---- reservoir MAC: CPW cached rows (SMEM) + rest streamed (L2) ----
        if (do_mac) {
            float acc[NVX];
#pragma unroll
            for (int i = 0; i < NVX; ++i) acc[i] = 0.f;
            if (k >= 1) {
#pragma unroll
                for (int rr = 0; rr < CPW; ++rr) {
                    const float4* w4 = reinterpret_cast<const float4*>(
                        &wc_s[(warp * CPW + rr) * 1024]) + lane;
                    acc[rr] = row_mac1(w4, xv, false);
                }
#pragma unroll
                for (int rr = CPW; rr < RPW; ++rr) {
                    const float4* w4 = reinterpret_cast<const float4*>(
                        w + (size_t)(r0 + warp * RPW + rr) * 1024) + lane;
                    acc[rr] = row_mac1(w4, xv, true);
                }
            }
            butterfly_reduce<NVX>(acc, lane);
            if ((lane & ((1 << SX) - 1)) == 0) {
                const float val = tanhf(uin_pref + acc[0]);
                const uint32_t la = smem_u32(&x_s[(k & 1) * 1024 + grow]);
#pragma unroll
                for (int rk = 0; rk < CS; ++rk) st_cluster_f32(la, rk, val);
            }
        }

        // ---- pca p_{k-1} = x_{k-1} . wpca (SMEM, transposed) ----
        if (do_pca) {
            float pa[NVP];
#pragma unroll
            for (int i = 0; i < NVP; ++i) pa[i] = 0.f;
#pragma unroll
            for (int cc = 0; cc < HCW; ++cc) {
                const float4* w4 = reinterpret_cast<const float4*>(
                    &wpca_s[(warp * HCW + cc) * 1024]) + lane;
                pa[cc] = row_mac1(w4, xv, false);
            }
            butterfly_reduce<NVP>(pa, lane);
            if ((lane & ((1 << SP) - 1)) == 0) {
                const int v   = lane >> SP;
                const int col = warp * HCW + v;
                const int hg  = hc0 + col;
                const uint32_t la = smem_u32(&p_s[((k - 1) & 1) * 256 + hg]);
#pragma unroll
                for (int rk = 0; rk < CS; ++rk) st_cluster_f32(la, rk, pa[0]);
            }
        }

        // ---- the ONLY sync: cluster barrier ----
        asm volatile("barrier.cluster.arrive.aligned;" ::: "memory");
        asm volatile("barrier.cluster.wait.aligned;"   ::: "memory");
    }
}

// ---------------------------------------------------------------------------
// Launch: 8 clusters x CS CTAs. CS=16 if allowed, else portable 8.
// ---------------------------------------------------------------------------
extern "C" void kernel_launch(void* const* d_in, const int* in_sizes, int n_in,
                              void* d_out, int out_size) {
    const float* u      = (const float*)d_in[0];
    const float* w_in   = (const float*)d_in[1];
    const float* w      = (const float*)d_in[2];
    const float* w_bias = (const float*)d_in[3];
    const float* w_pca  = (const float*)d_in[4];
    const float* wzp    = (const float*)d_in[5];
    const float* wzh    = (const float*)d_in[6];
    const float* bz     = (const float*)d_in[7];
    float* out = (float*)d_out;

    cudaFuncSetAttribute(uin_kernel,
                         cudaFuncAttributeMaxDynamicSharedMemorySize, UIN_SMEM);
    uin_kernel<<<dim3(4, 32), 256, UIN_SMEM>>>(u, w_in, w_bias);

    cudaFuncSetAttribute(esn_cluster<16>,
                         cudaFuncAttributeMaxDynamicSharedMemorySize,
                         ESN_SMEM_F(16));
    cudaFuncSetAttribute(esn_cluster<16>,
                         cudaFuncAttributeNonPortableClusterSizeAllowed, 1);
    cudaFuncSetAttribute(esn_cluster<8>,
                         cudaFuncAttributeMaxDynamicSharedMemorySize,
                         ESN_SMEM_F(8));

    int maxc = 0;
    {
        cudaLaunchConfig_t probe = {};
        probe.gridDim  = {128, 1, 1};
        probe.blockDim = {NTHR, 1, 1};
        probe.dynamicSmemBytes = ESN_SMEM_F(16);
        cudaError_t e = cudaOccupancyMaxPotentialClusterSize(
            &maxc, (const void*)esn_cluster<16>, &probe);
        if (e != cudaSuccess) { maxc = 0; cudaGetLastError(); }
    }

    cudaLaunchAttribute attrs[1];
    attrs[0].id = cudaLaunchAttributeClusterDimension;
    cudaLaunchConfig_t cfg = {};
    cfg.blockDim = {NTHR, 1, 1};
    cfg.attrs    = attrs;
    cfg.numAttrs = 1;

    if (maxc >= 16) {
        attrs[0].val.clusterDim = {16, 1, 1};
        cfg.gridDim  = {128, 1, 1};        // 8 clusters x 16 CTAs
        cfg.dynamicSmemBytes = ESN_SMEM_F(16);
        cudaLaunchKernelEx(&cfg, esn_cluster<16>, w, w_pca, wzp, wzh, bz, out);
    } else {
        attrs[0].val.clusterDim = {8, 1, 1};
        cfg.gridDim  = {64, 1, 1};         // 8 clusters x 8 CTAs
        cfg.dynamicSmemBytes = ESN_SMEM_F(8);
        cudaLaunchKernelEx(&cfg, esn_cluster<8>, w, w_pca, wzp, wzh, bz, out);
    }
}

// round 16
// speedup vs baseline: 1.3882x; 1.3882x over previous
#include <cuda_runtime.h>
#include <cuda_bf16.h>
#include <cstdint>

// Problem constants
#define T_STEPS 2048
#define R_DIM   1024
#define B_DIM   8
#define H_DIM   256
#define I_DIM   128
#define NTHR2   512

__device__ float g_uin[(size_t)T_STEPS * R_DIM * B_DIM];   // [t][r][b]

// ---------------------------------------------------------------------------
// Helpers
// ---------------------------------------------------------------------------
__device__ __forceinline__ uint32_t smem_u32(const void* p) {
    uint32_t a;
    asm("{ .reg .u64 t; cvta.to.shared.u64 t, %1; cvt.u32.u64 %0, t; }"
        : "=r"(a) : "l"(p));
    return a;
}
__device__ __forceinline__ void st_cluster_f32(uint32_t laddr, int rank, float v) {
    uint32_t rem;
    asm volatile("mapa.shared::cluster.u32 %0, %1, %2;"
                 : "=r"(rem) : "r"(laddr), "r"(rank));
    asm volatile("st.shared::cluster.f32 [%0], %1;" :: "r"(rem), "f"(v) : "memory");
}

__host__ __device__ constexpr int ilog2c(int n) {
    return n <= 1 ? 0 : 1 + ilog2c(n / 2);
}

// Butterfly reduction of N per-thread values across 32 lanes.
// Post: lane l holds the full sum of value index v = l >> log2(32/N).
template <int N>
__device__ __forceinline__ void butterfly_reduce(float* acc, int lane) {
    int n = N;
#pragma unroll
    for (int off = 16; off >= 1; off >>= 1) {
        if (n > 1) {
            const int h = n >> 1;
            const bool up = (lane & off) != 0;
#pragma unroll
            for (int i = 0; i < h; ++i) {
                float send = up ? acc[i] : acc[i + h];
                float recv = __shfl_xor_sync(0xffffffffu, send, off);
                if (up) acc[i + h] += recv; else acc[i] += recv;
            }
            if (up) {
#pragma unroll
                for (int i = 0; i < h; ++i) acc[i] = acc[i + h];
            }
            n = h;
        } else {
            acc[0] += __shfl_xor_sync(0xffffffffu, acc[0], off);
        }
    }
}

// ---------------------------------------------------------------------------
// Kernel A: uin[t][r][b] = u[b][t][:] . w_in[r][:] + w_bias[r]
// ---------------------------------------------------------------------------
#define UIN_WPAD 132
#define UIN_SMEM (256 * UIN_WPAD * 4 + B_DIM * I_DIM * 4)

__global__ void __launch_bounds__(256) uin_kernel(
    const float* __restrict__ u, const float* __restrict__ w_in,
    const float* __restrict__ w_bias)
{
    extern __shared__ float sm[];
    float* w_s = sm;
    float* u_s = sm + 256 * UIN_WPAD;

    const int tid = threadIdx.x;
    const int r0  = blockIdx.x * 256;
    const int t0  = blockIdx.y * 64;

    for (int j = tid; j < 256 * I_DIM; j += 256) {
        int row = j >> 7, i = j & 127;
        w_s[row * UIN_WPAD + i] = w_in[(r0 + row) * I_DIM + i];
    }
    const float bias = w_bias[r0 + tid];

    for (int tt = 0; tt < 64; ++tt) {
        const int t = t0 + tt;
        __syncthreads();
        for (int j = tid; j < B_DIM * I_DIM; j += 256) {
            int b = j >> 7, i = j & 127;
            u_s[j] = u[((size_t)b * T_STEPS + t) * I_DIM + i];
        }
        __syncthreads();

        float acc[B_DIM];
#pragma unroll
        for (int b = 0; b < B_DIM; ++b) acc[b] = bias;

        const float4* wrow = reinterpret_cast<const float4*>(&w_s[tid * UIN_WPAD]);
#pragma unroll 8
        for (int i4 = 0; i4 < I_DIM / 4; ++i4) {
            float4 w4 = wrow[i4];
#pragma unroll
            for (int b = 0; b < B_DIM; ++b) {
                float4 u4 = reinterpret_cast<const float4*>(&u_s[b * I_DIM])[i4];
                acc[b] = fmaf(w4.x, u4.x, acc[b]);
                acc[b] = fmaf(w4.y, u4.y, acc[b]);
                acc[b] = fmaf(w4.z, u4.z, acc[b]);
                acc[b] = fmaf(w4.w, u4.w, acc[b]);
            }
        }
        float* dst = &g_uin[((size_t)t * R_DIM + r0 + tid) * B_DIM];
        reinterpret_cast<float4*>(dst)[0] = make_float4(acc[0], acc[1], acc[2], acc[3]);
        reinterpret_cast<float4*>(dst)[1] = make_float4(acc[4], acc[5], acc[6], acc[7]);
    }
}

// ---------------------------------------------------------------------------
// Kernel B: 4 clusters x 16 CTAs, 2 batches per cluster, 512 threads/CTA.
// K=1024 split in 2 halves across warp pairs: warp w -> row-group (w&7),
// K-half (w>>3). Half-partials combine through SMEM. Gate on warps 0-7.
// SMEM floats: x_s[4096] p_s[1024] h_s[1024] wc_s[24576] wpca_s[16384]
//              wzp_s[4096] wzh_s[4096] bz_s[16] red_x[256] red_p[64]
// ---------------------------------------------------------------------------
#define CPW   3
#define ESN_SMEM16 ((4096 + 1024 + 1024 + 24576 + 16384 + 4096 + 4096 + 16 + 256 + 64) * 4)

// Half-row (512 wide) x 2 batches dot product, split accumulators.
__device__ __forceinline__ void row_mac2h(
    const float4* w4, const float* xa, const float* xb,
    bool from_global, float& oa, float& ob)
{
    float a0 = 0.f, a1 = 0.f, b0 = 0.f, b1 = 0.f;
    float a2 = 0.f, a3 = 0.f, b2 = 0.f, b3 = 0.f;
#pragma unroll
    for (int i = 0; i < 4; ++i) {
        const float4 w = from_global ? __ldcg(w4 + 32 * i) : w4[32 * i];
        a0 = fmaf(w.x, xa[4 * i + 0], a0);
        a1 = fmaf(w.y, xa[4 * i + 1], a1);
        a2 = fmaf(w.z, xa[4 * i + 2], a2);
        a3 = fmaf(w.w, xa[4 * i + 3], a3);
        b0 = fmaf(w.x, xb[4 * i + 0], b0);
        b1 = fmaf(w.y, xb[4 * i + 1], b1);
        b2 = fmaf(w.z, xb[4 * i + 2], b2);
        b3 = fmaf(w.w, xb[4 * i + 3], b3);
    }
    oa = (a0 + a1) + (a2 + a3);
    ob = (b0 + b1) + (b2 + b3);
}

__global__ void __launch_bounds__(NTHR2, 1) esn_cluster16(
    const float* __restrict__ w,
    const float* __restrict__ w_pca,
    const float* __restrict__ wzp,
    const float* __restrict__ wzh,
    const float* __restrict__ bz,
    float* __restrict__ out)
{
    constexpr int ROWS = 64;    // W rows per CTA
    constexpr int RPW  = 8;     // rows per row-group
    constexpr int HC   = 16;    // pca cols / gate rows per CTA
    constexpr int HCW  = 2;     // gate/pca rows per warp(-group)

    extern __shared__ float smf[];
    float* x_s    = smf;                 // [2][2][1024]
    float* p_s    = x_s + 4096;          // [2][2][256]
    float* h_s    = p_s + 1024;          // [2][2][256]
    float* wc_s   = h_s + 1024;          // [CPW*8][1024]
    float* wpca_s = wc_s + 24576;        // [HC][1024] transposed
    float* wzp_s  = wpca_s + 16384;      // [HC][256]
    float* wzh_s  = wzp_s + 4096;        // [HC][256]
    float* bz_s   = wzh_s + 4096;        // [HC]
    float* red_x  = bz_s + 16;           // [2][128]  (khalf, wg*16+v)
    float* red_p  = red_x + 256;         // [2][32]   (khalf, wg*4+v)

    const int tid  = threadIdx.x;
    const int warp = tid >> 5;
    const int lane = tid & 31;
    const int wg   = warp & 7;      // row group
    const int kh   = warp >> 3;     // K half
    unsigned cr;
    asm("mov.u32 %0, %%cluster_ctarank;" : "=r"(cr));
    const int crank = (int)cr;
    const int g   = blockIdx.x / 16;
    const int b0  = g * 2;
    const int r0  = crank * ROWS;
    const int hc0 = crank * HC;

    // ---- one-time staging ----
    for (int j = tid; j < 6144; j += NTHR2) smf[j] = 0.f;
    for (int idx = tid; idx < CPW * 8 * 256; idx += NTHR2) {
        const int rowi = idx >> 8;
        const int q    = idx & 255;
        const int w_   = rowi / CPW;
        const int rr   = rowi % CPW;
        const float4 v4 = *reinterpret_cast<const float4*>(
            &w[(size_t)(r0 + w_ * RPW + rr) * 1024 + 4 * q]);
        *reinterpret_cast<float4*>(&wc_s[rowi * 1024 + 4 * q]) = v4;
    }
    for (int idx = tid; idx < 1024 * (HC / 4); idx += NTHR2) {
        const int r = idx / (HC / 4);
        const int q = idx % (HC / 4);
        const float4 v4 = *reinterpret_cast<const float4*>(
            &w_pca[(size_t)r * H_DIM + hc0 + 4 * q]);
        wpca_s[(4 * q + 0) * 1024 + r] = v4.x;
        wpca_s[(4 * q + 1) * 1024 + r] = v4.y;
        wpca_s[(4 * q + 2) * 1024 + r] = v4.z;
        wpca_s[(4 * q + 3) * 1024 + r] = v4.w;
    }
    for (int j = tid; j < HC * 256; j += NTHR2) {
        const int row = j >> 8, q = j & 255;
        wzp_s[j] = wzp[(hc0 + row) * H_DIM + q];
        wzh_s[j] = wzh[(hc0 + row) * H_DIM + q];
    }
    if (tid < HC) bz_s[tid] = bz[hc0 + tid];
    __syncthreads();
    asm volatile("barrier.cluster.arrive.aligned;" ::: "memory");
    asm volatile("barrier.cluster.wait.aligned;"   ::: "memory");

    // ---- main loop ----
    for (int k = 0; k <= T_STEPS + 1; ++k) {
        const bool do_mac  = (k < T_STEPS);
        const bool do_pca  = (k >= 1 && k <= T_STEPS);
        const bool do_gate = (k >= 2);

        // uin prefetch by final writers (tid<128: wgw=tid>>4, v=tid&15)
        float uin_pref = 0.f;
        if (do_mac && tid < 128) {
            const int v    = tid & 15;
            const int grow = r0 + (tid >> 4) * RPW + (v >> 1);
            uin_pref = __ldcg(&g_uin[((size_t)k * R_DIM + grow) * 8 + b0 + (v & 1)]);
        }

        // ---- gate for t = k-2 (warps 0-7, full 256-wide K) ----
        if (do_gate && warp < 8) {
            const int t = k - 2;
            const float* pv = p_s + (t & 1) * 512;
            const float* hv = h_s + ((t + 1) & 1) * 512;
            const bool have_h = (t > 0);

            float ga[4] = {0.f, 0.f, 0.f, 0.f};
#pragma unroll
            for (int q = 0; q < 8; ++q) {
                const int j = lane + 32 * q;
                const float pj0 = pv[j],       pj1 = pv[256 + j];
                const float hj0 = have_h ? hv[j] : 0.f;
                const float hj1 = have_h ? hv[256 + j] : 0.f;
#pragma unroll
                for (int rr = 0; rr < HCW; ++rr) {
                    const int row = wg * HCW + rr;
                    const float wp = wzp_s[row * 256 + j];
                    const float wh = wzh_s[row * 256 + j];
                    ga[rr * 2 + 0] = fmaf(pj0, wp, fmaf(hj0, wh, ga[rr * 2 + 0]));
                    ga[rr * 2 + 1] = fmaf(pj1, wp, fmaf(hj1, wh, ga[rr * 2 + 1]));
                }
            }
            butterfly_reduce<4>(ga, lane);
            if ((lane & 7) == 0) {
                const int v   = lane >> 3;
                const int row = wg * HCW + (v >> 1);
                const int b   = v & 1;
                const int hg  = hc0 + row;
                const float s = ga[0] + bz_s[row];
                const float z = 1.f / (1.f + __expf(-s));
                const float po = pv[b * 256 + hg];
                const float ho = have_h ? hv[b * 256 + hg] : 0.f;
                const float hn = (1.f - z) * ho + z * po;
                const uint32_t la = smem_u32(&h_s[(t & 1) * 512 + b * 256 + hg]);
#pragma unroll
                for (int rk = 0; rk < 16; ++rk) st_cluster_f32(la, rk, hn);
                out[((size_t)(b0 + b) * T_STEPS + t) * H_DIM + hg] = hn;
            }
        }

        // ---- load this warp's K-half of x_{k-1} (both batches) ----
        float xa[16], xb[16];
        if (do_pca) {
            const float* x0 = x_s + ((k + 1) & 1) * 2048 + kh * 512;
            const float* x1 = x0 + 1024;
#pragma unroll
            for (int i = 0; i < 4; ++i) {
                const float4 a = *reinterpret_cast<const float4*>(&x0[4 * lane + 128 * i]);
                const float4 b = *reinterpret_cast<const float4*>(&x1[4 * lane + 128 * i]);
                xa[4 * i + 0] = a.x; xa[4 * i + 1] = a.y;
                xa[4 * i + 2] = a.z; xa[4 * i + 3] = a.w;
                xb[4 * i + 0] = b.x; xb[4 * i + 1] = b.y;
                xb[4 * i + 2] = b.z; xb[4 * i + 3] = b.w;
            }
        }

        // ---- reservoir MAC (half-K partials) ----
        if (do_mac) {
            float acc[16];
#pragma unroll
            for (int i = 0; i < 16; ++i) acc[i] = 0.f;
            if (k >= 1) {
#pragma unroll
                for (int rr = 0; rr < CPW; ++rr) {
                    const float4* w4 = reinterpret_cast<const float4*>(
                        &wc_s[(wg * CPW + rr) * 1024 + kh * 512]) + lane;
                    row_mac2h(w4, xa, xb, false, acc[rr * 2], acc[rr * 2 + 1]);
                }
#pragma unroll
                for (int rr = CPW; rr < RPW; ++rr) {
                    const float4* w4 = reinterpret_cast<const float4*>(
                        w + (size_t)(r0 + wg * RPW + rr) * 1024 + kh * 512) + lane;
                    row_mac2h(w4, xa, xb, true, acc[rr * 2], acc[rr * 2 + 1]);
                }
            }
            butterfly_reduce<16>(acc, lane);
            if ((lane & 1) == 0)
                red_x[kh * 128 + wg * 16 + (lane >> 1)] = acc[0];
        }

        // ---- pca (half-K partials) ----
        if (do_pca) {
            float pa[4] = {0.f, 0.f, 0.f, 0.f};
#pragma unroll
            for (int cc = 0; cc < HCW; ++cc) {
                const float4* w4 = reinterpret_cast<const float4*>(
                    &wpca_s[(wg * HCW + cc) * 1024 + kh * 512]) + lane;
                row_mac2h(w4, xa, xb, false, pa[cc * 2], pa[cc * 2 + 1]);
            }
            butterfly_reduce<4>(pa, lane);
            if ((lane & 7) == 0)
                red_p[kh * 32 + wg * 4 + (lane >> 3)] = pa[0];
        }
        __syncthreads();

        // ---- combine K-halves, finalize, DSMEM broadcast ----
        if (do_mac && tid < 128) {
            const int v    = tid & 15;
            const int mrow = v >> 1;
            const int mb   = v & 1;
            const int grow = r0 + (tid >> 4) * RPW + mrow;
            const float s = red_x[tid] + red_x[128 + tid];
            const float val = tanhf(uin_pref + s);
            const uint32_t la = smem_u32(&x_s[(k & 1) * 2048 + mb * 1024 + grow]);
#pragma unroll
            for (int rk = 0; rk < 16; ++rk) st_cluster_f32(la, rk, val);
        }
        if (do_pca && tid < 32) {
            const int v   = tid & 3;
            const int col = (tid >> 2) * HCW + (v >> 1);
            const int b   = v & 1;
            const int hg  = hc0 + col;
            const float s = red_p[tid] + red_p[32 + tid];
            const uint32_t la = smem_u32(&p_s[((k - 1) & 1) * 512 + b * 256 + hg]);
#pragma unroll
            for (int rk = 0; rk < 16; ++rk) st_cluster_f32(la, rk, s);
        }

        // ---- the ONLY sync: cluster barrier ----
        asm volatile("barrier.cluster.arrive.aligned;" ::: "memory");
        asm volatile("barrier.cluster.wait.aligned;"   ::: "memory");
    }
}

// ---------------------------------------------------------------------------
// Launch
// ---------------------------------------------------------------------------
extern "C" void kernel_launch(void* const* d_in, const int* in_sizes, int n_in,
                              void* d_out, int out_size) {
    const float* u      = (const float*)d_in[0];
    const float* w_in   = (const float*)d_in[1];
    const float* w      = (const float*)d_in[2];
    const float* w_bias = (const float*)d_in[3];
    const float* w_pca  = (const float*)d_in[4];
    const float* wzp    = (const float*)d_in[5];
    const float* wzh    = (const float*)d_in[6];
    const float* bz     = (const float*)d_in[7];
    float* out = (float*)d_out;

    cudaFuncSetAttribute(uin_kernel,
                         cudaFuncAttributeMaxDynamicSharedMemorySize, UIN_SMEM);
    uin_kernel<<<dim3(4, 32), 256, UIN_SMEM>>>(u, w_in, w_bias);

    cudaFuncSetAttribute(esn_cluster16,
                         cudaFuncAttributeMaxDynamicSharedMemorySize, ESN_SMEM16);
    cudaFuncSetAttribute(esn_cluster16,
                         cudaFuncAttributeNonPortableClusterSizeAllowed, 1);

    cudaLaunchAttribute attrs[1];
    attrs[0].id = cudaLaunchAttributeClusterDimension;
    attrs[0].val.clusterDim = {16, 1, 1};
    cudaLaunchConfig_t cfg = {};
    cfg.gridDim  = {64, 1, 1};            // 4 clusters x 16 CTAs
    cfg.blockDim = {NTHR2, 1, 1};
    cfg.dynamicSmemBytes = ESN_SMEM16;
    cfg.attrs    = attrs;
    cfg.numAttrs = 1;
    cudaLaunchKernelEx(&cfg, esn_cluster16, w, w_pca, wzp, wzh, bz, out);
}